// round 13
// baseline (speedup 1.0000x reference)
#include <cuda_runtime.h>
#include <math.h>

// feat: [B=4, C=256, H=50, W=50] f32;  rois: [R,5] f32;  out: [R,256,7,7] f32
#define CC 256
#define HW 2500
#define HH 50
#define WW 50
#define PP 7
#define NBIN 49
#define SPATIAL_SCALE 0.0625f
#define NT 256

// Single fused kernel. Block = (k, r): covers 256 outputs of ROI r
// (outputs il = k*256+t, c = il/49, p = il%49). Threads t<49 rebuild the
// per-bin geometry in smem (no setup kernel, no table-LDG dependency).
__global__ void __launch_bounds__(NT)
roipool_kernel(const float* __restrict__ feat,
               const float* __restrict__ rois,
               float* __restrict__ out) {
    __shared__ int s_off[NBIN];     // hs*50 + ps*2 (pair-aligned base offset)
    __shared__ unsigned s_msk[NBIN];// 24-bit mask: bit(i*6+j) = row i, col j valid
    __shared__ int s_b;             // b * CC * HW

    const int k = blockIdx.x;       // 0..48
    const int r = blockIdx.y;       // roi
    const int t = threadIdx.x;

    if (t < NBIN) {
        const float* rp = rois + (size_t)r * 5;
        // jnp.round == round-half-to-even == rintf (RN); *0.0625 exact.
        float x1 = rintf(rp[1] * SPATIAL_SCALE);
        float y1 = rintf(rp[2] * SPATIAL_SCALE);
        float x2 = rintf(rp[3] * SPATIAL_SCALE);
        float y2 = rintf(rp[4] * SPATIAL_SCALE);
        // XLA folds x/7 into x * RN(1/7); replicate exactly.
        const float INV7 = 1.0f / 7.0f;
        float bw = __fmul_rn(fmaxf(x2 - x1 + 1.0f, 1.0f), INV7);
        float bh = __fmul_rn(fmaxf(y2 - y1 + 1.0f, 1.0f), INV7);
        float fpw = (float)(t % PP);
        float fph = (float)(t / PP);
        int ws = (int)fminf(fmaxf(floorf(__fmul_rn(bw, fpw))        + x1, 0.0f), (float)WW);
        int we = (int)fminf(fmaxf(ceilf (__fmul_rn(bw, fpw + 1.0f)) + x1, 0.0f), (float)WW);
        int hs = (int)fminf(fmaxf(floorf(__fmul_rn(bh, fph))        + y1, 0.0f), (float)HH);
        int he = (int)fminf(fmaxf(ceilf (__fmul_rn(bh, fph + 1.0f)) + y1, 0.0f), (float)HH);

        int nw = we - ws;           // 0..4 (window provably <= 4x4)
        int nh = he - hs;           // 0..4
        int ps = ws >> 1;           // first aligned float2 pair

        // Column bits within 6-col pair window, then replicate over nh rows.
        unsigned colbits = (nw > 0) ? (((1u << nw) - 1u) << (ws - ps * 2)) : 0u;
        unsigned rowrep  = (nh > 0) ? (0x041041u & ((1u << (6 * nh)) - 1u)) : 0u;
        s_msk[t] = colbits * rowrep;      // bit(i*6+j)
        s_off[t] = hs * WW + ps * 2;      // even -> float2-aligned
        if (t == 0) s_b = (int)rois[(size_t)r * 5] * (CC * HW);
    }
    __syncthreads();

    const int il = k * NT + t;      // 0..12543
    const int c  = il / NBIN;
    const int p  = il - c * NBIN;

    const unsigned mask = s_msk[p];
    const float2* base = (const float2*)(feat + s_b + c * HW + s_off[p]);

    // 4 rows x 3 aligned float2 pairs, predicated loads + predicated fmax.
    // Pair-load bit is the OR of its element bits, so a skipped load never
    // feeds a live fmax. Two accumulators (x-cols / y-cols) for ILP.
    float m0 = -INFINITY, m1 = -INFINITY;
    #pragma unroll
    for (int i = 0; i < 4; ++i) {
        const unsigned rm = mask >> (6 * i);
        const float2* row = base + i * (WW / 2);
        float2 v0, v1, v2;
        if (rm & 0x03u) v0 = __ldg(row + 0);
        if (rm & 0x0Cu) v1 = __ldg(row + 1);
        if (rm & 0x30u) v2 = __ldg(row + 2);
        if (rm & 0x01u) m0 = fmaxf(m0, v0.x);
        if (rm & 0x02u) m1 = fmaxf(m1, v0.y);
        if (rm & 0x04u) m0 = fmaxf(m0, v1.x);
        if (rm & 0x08u) m1 = fmaxf(m1, v1.y);
        if (rm & 0x10u) m0 = fmaxf(m0, v2.x);
        if (rm & 0x20u) m1 = fmaxf(m1, v2.y);
    }
    float m = fmaxf(m0, m1);

    // Coalesced store: out index = r*12544 + il (consecutive t -> consecutive).
    out[(size_t)r * (CC * NBIN) + il] = (m == -INFINITY) ? 0.0f : m;
}

extern "C" void kernel_launch(void* const* d_in, const int* in_sizes, int n_in,
                              void* d_out, int out_size) {
    const float* feat = (const float*)d_in[0];
    const float* rois = (const float*)d_in[1];
    float* out = (float*)d_out;

    int R = in_sizes[1] / 5;                 // 128
    dim3 grid(NBIN, R);                      // 49 x 128 = 6272 blocks
    roipool_kernel<<<grid, NT>>>(feat, rois, out);
}